// round 3
// baseline (speedup 1.0000x reference)
#include <cuda_runtime.h>
#include <math.h>

// Problem constants
#define BB 8
#define NN 1024
#define MM 1024
#define D  512
#define HH 8
#define DS 64
#define ROWS (BB*NN)          // 8192
#define NEGV (-1e38f)
#define SCALE 0.04419417382415922f   // 1/sqrt(512)

// Scratch (device globals; no allocation allowed)
__device__ float S_xz[ROWS*D];
__device__ float S_yz[ROWS*D];
__device__ float S_q [ROWS*D];
__device__ float S_k [ROWS*D];
__device__ float S_v [ROWS*D];
__device__ float S_att[ROWS*D];

// ---------------------------------------------------------------------------
// Masked copy: dst[r,c] = mask[r] ? 0 : src[r,c]   (vectorized float4)
// ---------------------------------------------------------------------------
__global__ void __launch_bounds__(256) mask_copy_k(
    const float* __restrict__ src, const int* __restrict__ mask,
    float* __restrict__ dst)
{
    int i4 = blockIdx.x * 256 + threadIdx.x;     // over ROWS*D/4 = 1048576
    int row = i4 >> 7;                           // 128 float4 per row (D=512)
    float4 v = ((const float4*)src)[i4];
    if (mask[row]) v = make_float4(0.f, 0.f, 0.f, 0.f);
    ((float4*)dst)[i4] = v;
}

// ---------------------------------------------------------------------------
// SGEMM: C[ROWS,512] = A[ROWS,512] @ B[512,512]  (+bias, +relu via FLAGS)
// 64x64 tile, 16 k-slice, 256 threads, 4x4 microtile
// ---------------------------------------------------------------------------
template<int FLAGS>
__global__ void __launch_bounds__(256) sgemm_k(
    const float* __restrict__ A, const float* __restrict__ Bmat,
    const float* __restrict__ bias, float* __restrict__ C)
{
    __shared__ float As[16][68];
    __shared__ float Bs[16][64];
    const int t  = threadIdx.x;
    const int tx = t & 15, ty = t >> 4;
    const int row0 = blockIdx.y * 64, col0 = blockIdx.x * 64;
    const int am = t >> 2, ak = (t & 3) * 4;    // A-tile load: row am, cols ak..ak+3
    const int bk = t >> 4, bn = (t & 15) * 4;   // B-tile load: row bk, cols bn..bn+3

    float acc[4][4] = {};

    for (int k0 = 0; k0 < D; k0 += 16) {
        float4 av = *(const float4*)&A[(size_t)(row0 + am) * D + k0 + ak];
        As[ak+0][am] = av.x; As[ak+1][am] = av.y;
        As[ak+2][am] = av.z; As[ak+3][am] = av.w;
        float4 bv = *(const float4*)&Bmat[(size_t)(k0 + bk) * D + col0 + bn];
        *(float4*)&Bs[bk][bn] = bv;
        __syncthreads();
        #pragma unroll
        for (int kk = 0; kk < 16; kk++) {
            float4 a = *(const float4*)&As[kk][ty * 4];
            float4 b = *(const float4*)&Bs[kk][tx * 4];
            acc[0][0] += a.x*b.x; acc[0][1] += a.x*b.y; acc[0][2] += a.x*b.z; acc[0][3] += a.x*b.w;
            acc[1][0] += a.y*b.x; acc[1][1] += a.y*b.y; acc[1][2] += a.y*b.z; acc[1][3] += a.y*b.w;
            acc[2][0] += a.z*b.x; acc[2][1] += a.z*b.y; acc[2][2] += a.z*b.z; acc[2][3] += a.z*b.w;
            acc[3][0] += a.w*b.x; acc[3][1] += a.w*b.y; acc[3][2] += a.w*b.z; acc[3][3] += a.w*b.w;
        }
        __syncthreads();
    }

    #pragma unroll
    for (int i = 0; i < 4; i++) {
        float vv[4];
        #pragma unroll
        for (int j = 0; j < 4; j++) {
            float x = acc[i][j];
            if (FLAGS & 1) x += bias[col0 + tx * 4 + j];
            if (FLAGS & 2) x = fmaxf(x, 0.f);
            vv[j] = x;
        }
        *(float4*)&C[(size_t)(row0 + ty * 4 + i) * D + col0 + tx * 4] =
            make_float4(vv[0], vv[1], vv[2], vv[3]);
    }
}

// ---------------------------------------------------------------------------
// Flash attention: one CTA = (b,h, 64-query tile). Online softmax over M=1024.
// q,k,v: [B,{N,M},512] (head h occupies cols h*64..h*64+63)
// att out: same layout; query-masked rows written as 0.
// ---------------------------------------------------------------------------
__global__ void __launch_bounds__(256) attn_k(
    const float* __restrict__ q, const float* __restrict__ k,
    const float* __restrict__ v,
    const int* __restrict__ xmask,
    const int* __restrict__ ymask,
    float* __restrict__ att)
{
    extern __shared__ float sm[];
    float* Qs   = sm;                // [64][68]  layout [d][r]
    float* Ks   = Qs + 64 * 68;      // [64][68]  layout [d][c]
    float* Vs   = Ks + 64 * 68;      // [64][68]  layout [m][dim]
    float* Ss   = Vs + 64 * 68;      // [64][68]  layout [m][r]
    float* mi   = Ss + 64 * 68;      // [64]
    float* li   = mi + 64;           // [64]
    float* corr = li + 64;           // [64]

    const int bh = blockIdx.y;
    const int b  = bh >> 3, h = bh & 7;
    const int n0 = blockIdx.x * 64;
    const int t  = threadIdx.x;
    const int tx = t & 15, ty = t >> 4;

    const float* qbase = q + ((size_t)b * NN + n0) * D + h * DS;
    const float* kbase = k + (size_t)b * MM * D + h * DS;
    const float* vbase = v + (size_t)b * MM * D + h * DS;
    const int* ymb = ymask + b * MM;
    const int* xmb = xmask + b * NN;

    // Load Q tile transposed into [d][r] — full 64x64: 4 float4 per thread
    {
        int r = t >> 2;
        #pragma unroll
        for (int dd = 0; dd < 4; dd++) {
            int d4 = (t & 3) * 4 + dd * 16;
            float4 qa = *(const float4*)&qbase[(size_t)r * D + d4];
            Qs[(d4+0)*68 + r] = qa.x; Qs[(d4+1)*68 + r] = qa.y;
            Qs[(d4+2)*68 + r] = qa.z; Qs[(d4+3)*68 + r] = qa.w;
        }
    }
    if (t < 64) { mi[t] = -3.0e38f; li[t] = 0.f; }

    float acc[4][4] = {};

    for (int m0 = 0; m0 < MM; m0 += 64) {
        __syncthreads();   // protect Ks/Vs/Ss from previous iteration readers
        {
            int r = t >> 2;
            #pragma unroll
            for (int dd = 0; dd < 4; dd++) {
                int d4 = (t & 3) * 4 + dd * 16;
                float4 kv = *(const float4*)&kbase[(size_t)(m0 + r) * D + d4];
                Ks[(d4+0)*68 + r] = kv.x; Ks[(d4+1)*68 + r] = kv.y;
                Ks[(d4+2)*68 + r] = kv.z; Ks[(d4+3)*68 + r] = kv.w;
                float4 vv = *(const float4*)&vbase[(size_t)(m0 + r) * D + d4];
                *(float4*)&Vs[r * 68 + d4] = vv;
            }
        }
        __syncthreads();

        // S = Q.K^T (4x4 per thread)
        float s[4][4] = {};
        #pragma unroll 8
        for (int d = 0; d < 64; d++) {
            float4 a = *(const float4*)&Qs[d * 68 + ty * 4];
            float4 bq = *(const float4*)&Ks[d * 68 + tx * 4];
            s[0][0] += a.x*bq.x; s[0][1] += a.x*bq.y; s[0][2] += a.x*bq.z; s[0][3] += a.x*bq.w;
            s[1][0] += a.y*bq.x; s[1][1] += a.y*bq.y; s[1][2] += a.y*bq.z; s[1][3] += a.y*bq.w;
            s[2][0] += a.z*bq.x; s[2][1] += a.z*bq.y; s[2][2] += a.z*bq.z; s[2][3] += a.z*bq.w;
            s[3][0] += a.w*bq.x; s[3][1] += a.w*bq.y; s[3][2] += a.w*bq.z; s[3][3] += a.w*bq.w;
        }

        // scale, key-mask, store transposed Ss[m][r]
        #pragma unroll
        for (int j = 0; j < 4; j++) {
            int c = tx * 4 + j;
            bool km = ymb[m0 + c] != 0;
            #pragma unroll
            for (int i = 0; i < 4; i++) {
                float val = km ? NEGV : s[i][j] * SCALE;
                Ss[c * 68 + ty * 4 + i] = val;
            }
        }
        __syncthreads();

        // Online softmax row pass (64 rows, one thread each)
        if (t < 64) {
            int r = t;
            float mold = mi[r];
            float mx = mold;
            for (int c = 0; c < 64; c++) mx = fmaxf(mx, Ss[c * 68 + r]);
            float co = __expf(mold - mx);
            float sum = 0.f;
            for (int c = 0; c < 64; c++) {
                float p = __expf(Ss[c * 68 + r] - mx);
                Ss[c * 68 + r] = p;
                sum += p;
            }
            li[r] = li[r] * co + sum;
            mi[r] = mx;
            corr[r] = co;
        }
        __syncthreads();

        // rescale accumulators, then acc += P.V
        #pragma unroll
        for (int i = 0; i < 4; i++) {
            float co = corr[ty * 4 + i];
            acc[i][0] *= co; acc[i][1] *= co; acc[i][2] *= co; acc[i][3] *= co;
        }
        #pragma unroll 8
        for (int m = 0; m < 64; m++) {
            float4 a = *(const float4*)&Ss[m * 68 + ty * 4];
            float4 bv = *(const float4*)&Vs[m * 68 + tx * 4];
            acc[0][0] += a.x*bv.x; acc[0][1] += a.x*bv.y; acc[0][2] += a.x*bv.z; acc[0][3] += a.x*bv.w;
            acc[1][0] += a.y*bv.x; acc[1][1] += a.y*bv.y; acc[1][2] += a.y*bv.z; acc[1][3] += a.y*bv.w;
            acc[2][0] += a.z*bv.x; acc[2][1] += a.z*bv.y; acc[2][2] += a.z*bv.z; acc[2][3] += a.z*bv.w;
            acc[3][0] += a.w*bv.x; acc[3][1] += a.w*bv.y; acc[3][2] += a.w*bv.z; acc[3][3] += a.w*bv.w;
        }
    }
    __syncthreads();

    // Writeout: att = acc / li, query-masked rows -> 0
    float* obase = att + ((size_t)b * NN + n0) * D + h * DS;
    #pragma unroll
    for (int i = 0; i < 4; i++) {
        int r = ty * 4 + i;
        float inv = 1.f / li[r];
        bool qm = xmb[n0 + r] != 0;
        float4 o;
        o.x = qm ? 0.f : acc[i][0] * inv;
        o.y = qm ? 0.f : acc[i][1] * inv;
        o.z = qm ? 0.f : acc[i][2] * inv;
        o.w = qm ? 0.f : acc[i][3] * inv;
        *(float4*)&obase[(size_t)r * D + tx * 4] = o;
    }
}

// ---------------------------------------------------------------------------
// out = LN(a + b) * g + be, optional row-mask -> 0. One CTA per row, 128 thr.
// ---------------------------------------------------------------------------
__global__ void __launch_bounds__(128) add_ln_k(
    const float* __restrict__ a, const float* __restrict__ bsrc,
    const float* __restrict__ g, const float* __restrict__ be,
    const int* __restrict__ xmask, int use_mask,
    float* __restrict__ out)
{
    int row = blockIdx.x;
    int t = threadIdx.x;
    const float* ar = a + (size_t)row * D;
    const float* br = bsrc + (size_t)row * D;

    float vals[4];
    float s = 0.f;
    #pragma unroll
    for (int i = 0; i < 4; i++) {
        vals[i] = ar[t + i * 128] + br[t + i * 128];
        s += vals[i];
    }
    __shared__ float red[4];
    #pragma unroll
    for (int o = 16; o; o >>= 1) s += __shfl_xor_sync(0xffffffffu, s, o);
    if ((t & 31) == 0) red[t >> 5] = s;
    __syncthreads();
    float mu = (red[0] + red[1] + red[2] + red[3]) * (1.f / 512.f);

    float s2 = 0.f;
    #pragma unroll
    for (int i = 0; i < 4; i++) { float d = vals[i] - mu; s2 += d * d; }
    __syncthreads();
    #pragma unroll
    for (int o = 16; o; o >>= 1) s2 += __shfl_xor_sync(0xffffffffu, s2, o);
    if ((t & 31) == 0) red[t >> 5] = s2;
    __syncthreads();
    float inv = rsqrtf((red[0] + red[1] + red[2] + red[3]) * (1.f / 512.f) + 1e-5f);

    bool msk = use_mask && (xmask[row] != 0);
    #pragma unroll
    for (int i = 0; i < 4; i++) {
        int c = t + i * 128;
        out[(size_t)row * D + c] = msk ? 0.f : (vals[i] - mu) * inv * g[c] + be[c];
    }
}

// ---------------------------------------------------------------------------
extern "C" void kernel_launch(void* const* d_in, const int* in_sizes, int n_in,
                              void* d_out, int out_size)
{
    const float* x  = (const float*)d_in[0];
    const float* y  = (const float*)d_in[1];
    const int* xm = (const int*)d_in[2];
    const int* ym = (const int*)d_in[3];
    const float* Wq = (const float*)d_in[4];
    const float* Wk = (const float*)d_in[5];
    const float* Wv = (const float*)d_in[6];
    const float* Wo = (const float*)d_in[7];
    const float* W1 = (const float*)d_in[8];
    const float* b1 = (const float*)d_in[9];
    const float* W2 = (const float*)d_in[10];
    const float* b2 = (const float*)d_in[11];
    const float* g1 = (const float*)d_in[12];
    const float* be1= (const float*)d_in[13];
    const float* g2 = (const float*)d_in[14];
    const float* be2= (const float*)d_in[15];
    float* out = (float*)d_out;

    float *xz, *yz, *q, *k, *v, *att;
    cudaGetSymbolAddress((void**)&xz,  S_xz);
    cudaGetSymbolAddress((void**)&yz,  S_yz);
    cudaGetSymbolAddress((void**)&q,   S_q);
    cudaGetSymbolAddress((void**)&k,   S_k);
    cudaGetSymbolAddress((void**)&v,   S_v);
    cudaGetSymbolAddress((void**)&att, S_att);

    cudaFuncSetAttribute(attn_k, cudaFuncAttributeMaxDynamicSharedMemorySize, 72000);

    const int smem_attn = (4 * 64 * 68 + 3 * 64) * sizeof(float); // 70400 B

    mask_copy_k<<<4096, 256>>>(x, xm, xz);
    mask_copy_k<<<4096, 256>>>(y, ym, yz);

    dim3 gg(8, 128);   // cols x rows of 64x64 tiles
    sgemm_k<0><<<gg, 256>>>(xz, Wq, nullptr, q);
    sgemm_k<0><<<gg, 256>>>(yz, Wk, nullptr, k);
    sgemm_k<0><<<gg, 256>>>(yz, Wv, nullptr, v);

    dim3 ga(16, 64);   // 16 q-tiles x (B*H) blocks
    attn_k<<<ga, 256, smem_attn>>>(q, k, v, xm, ym, att);

    sgemm_k<0><<<gg, 256>>>(att, Wo, nullptr, q);        // q := att@Wo
    add_ln_k<<<ROWS, 128>>>(xz, q, g1, be1, nullptr, 0, k);  // k := o = LN1(x+attWo)
    sgemm_k<3><<<gg, 256>>>(k, W1, b1, v);               // v := relu(o@W1+b1)
    sgemm_k<1><<<gg, 256>>>(v, W2, b2, att);             // att := ff
    add_ln_k<<<ROWS, 128>>>(k, att, g2, be2, xm, 1, out);
}

// round 4
// speedup vs baseline: 1.1114x; 1.1114x over previous
#include <cuda_runtime.h>
#include <math.h>

#define BB 8
#define NN 1024
#define MM 1024
#define D  512
#define HH 8
#define DS 64
#define ROWS (BB*NN)          // 8192
#define NEGV (-1e38f)
#define SCALE 0.04419417382415922f   // 1/sqrt(512)

// Scratch (device globals; no allocation allowed)
__device__ float S_q  [ROWS*D];
__device__ float S_k  [ROWS*D];
__device__ float S_v  [ROWS*D];
__device__ float S_att[ROWS*D];
__device__ float S_t1 [ROWS*D];
__device__ float S_t2 [ROWS*D];

// ---------------------------------------------------------------------------
// SGEMM: C[ROWS,512] = A[ROWS,512] @ B[512,512]
// FLAGS: bit0 = +bias, bit1 = relu, bit2 = zero A rows where amask[row]!=0
// 128x128 tile, k-chunk 8, 256 threads, 8x8 microtile (2x2 blocks of 4x4),
// double-buffered smem.
// ---------------------------------------------------------------------------
template<int FLAGS>
__global__ void __launch_bounds__(256) sgemm128(
    const float* __restrict__ A, const float* __restrict__ Bmat,
    const float* __restrict__ bias, const int* __restrict__ amask,
    float* __restrict__ C)
{
    __shared__ float As[2][8][132];
    __shared__ float Bs[2][8][132];
    const int t  = threadIdx.x;
    const int tx = t & 15, ty = t >> 4;
    const int row0 = blockIdx.y * 128, col0 = blockIdx.x * 128;
    const int ar = t >> 1, ak = (t & 1) * 4;    // A: 2 threads/row, 8 k-cols
    const int bk = t >> 5, bn = (t & 31) * 4;   // B: 8 k-rows, 32 threads/row

    const bool am = (FLAGS & 4) && (amask[row0 + ar] != 0);
    const float* Aptr = A + (size_t)(row0 + ar) * D + ak;
    const float* Bptr = Bmat + (size_t)bk * D + col0 + bn;

    float4 av = *(const float4*)Aptr;
    float4 bv = *(const float4*)Bptr;
    if (am) av = make_float4(0.f, 0.f, 0.f, 0.f);
    As[0][ak+0][ar] = av.x; As[0][ak+1][ar] = av.y;
    As[0][ak+2][ar] = av.z; As[0][ak+3][ar] = av.w;
    *(float4*)&Bs[0][bk][bn] = bv;
    __syncthreads();

    float acc[8][8] = {};   // [rb*4+i][cb*4+j]

    #pragma unroll 1
    for (int c = 0; c < 64; c++) {
        int cur = c & 1;
        if (c < 63) {
            av = *(const float4*)(Aptr + (c + 1) * 8);
            bv = *(const float4*)(Bptr + (size_t)(c + 1) * 8 * D);
            if (am) av = make_float4(0.f, 0.f, 0.f, 0.f);
        }
        #pragma unroll
        for (int kk = 0; kk < 8; kk++) {
            float4 a0 = *(const float4*)&As[cur][kk][ty * 4];
            float4 a1 = *(const float4*)&As[cur][kk][64 + ty * 4];
            float4 b0 = *(const float4*)&Bs[cur][kk][tx * 4];
            float4 b1 = *(const float4*)&Bs[cur][kk][64 + tx * 4];
            float ra[8] = {a0.x,a0.y,a0.z,a0.w,a1.x,a1.y,a1.z,a1.w};
            float rb[8] = {b0.x,b0.y,b0.z,b0.w,b1.x,b1.y,b1.z,b1.w};
            #pragma unroll
            for (int i = 0; i < 8; i++)
                #pragma unroll
                for (int j = 0; j < 8; j++)
                    acc[i][j] += ra[i] * rb[j];
        }
        if (c < 63) {
            int nxt = cur ^ 1;
            As[nxt][ak+0][ar] = av.x; As[nxt][ak+1][ar] = av.y;
            As[nxt][ak+2][ar] = av.z; As[nxt][ak+3][ar] = av.w;
            *(float4*)&Bs[nxt][bk][bn] = bv;
            __syncthreads();
        }
    }

    #pragma unroll
    for (int rb = 0; rb < 2; rb++)
    #pragma unroll
    for (int i = 0; i < 4; i++) {
        int row = row0 + rb * 64 + ty * 4 + i;
        #pragma unroll
        for (int cb = 0; cb < 2; cb++) {
            int col = col0 + cb * 64 + tx * 4;
            float vv[4];
            #pragma unroll
            for (int j = 0; j < 4; j++) {
                float x = acc[rb * 4 + i][cb * 4 + j];
                if (FLAGS & 1) x += bias[col + j];
                if (FLAGS & 2) x = fmaxf(x, 0.f);
                vv[j] = x;
            }
            *(float4*)&C[(size_t)row * D + col] =
                make_float4(vv[0], vv[1], vv[2], vv[3]);
        }
    }
}

// ---------------------------------------------------------------------------
// Flash attention: one CTA = (b,h, 64-query tile). Online softmax over M=1024.
// Softmax entirely in registers via shfl reductions over the 16 tx lanes.
// ---------------------------------------------------------------------------
__global__ void __launch_bounds__(256) attn_k(
    const float* __restrict__ q, const float* __restrict__ k,
    const float* __restrict__ v,
    const int* __restrict__ xmask,
    const int* __restrict__ ymask,
    float* __restrict__ att)
{
    extern __shared__ float sm[];
    float* Qs = sm;              // [64][68]  [d][r], pre-scaled by SCALE
    float* Ks = Qs + 64 * 68;    // [64][68]  [d][c]
    float* Vs = Ks + 64 * 68;    // [64][68]  [m][d]
    float* Ss = Vs + 64 * 68;    // [64][68]  [m][r]  (exp'd P)

    const int bh = blockIdx.y;
    const int b  = bh >> 3, h = bh & 7;
    const int n0 = blockIdx.x * 64;
    const int t  = threadIdx.x;
    const int tx = t & 15, ty = t >> 4;

    const float* qbase = q + ((size_t)b * NN + n0) * D + h * DS;
    const float* kbase = k + (size_t)b * MM * D + h * DS;
    const float* vbase = v + (size_t)b * MM * D + h * DS;
    const int* ymb = ymask + b * MM;
    const int* xmb = xmask + b * NN;

    // Load Q tile transposed into [d][r], scaled
    {
        int r = t >> 2;
        #pragma unroll
        for (int dd = 0; dd < 4; dd++) {
            int d4 = (t & 3) * 4 + dd * 16;
            float4 qa = *(const float4*)&qbase[(size_t)r * D + d4];
            Qs[(d4+0)*68 + r] = qa.x * SCALE; Qs[(d4+1)*68 + r] = qa.y * SCALE;
            Qs[(d4+2)*68 + r] = qa.z * SCALE; Qs[(d4+3)*68 + r] = qa.w * SCALE;
        }
    }

    float mi[4] = {-3.0e38f, -3.0e38f, -3.0e38f, -3.0e38f};
    float li[4] = {0.f, 0.f, 0.f, 0.f};
    float acc[4][4] = {};

    for (int m0 = 0; m0 < MM; m0 += 64) {
        __syncthreads();   // protect Ks/Vs/Ss from previous iteration readers
        {
            int r = t >> 2;
            #pragma unroll
            for (int dd = 0; dd < 4; dd++) {
                int d4 = (t & 3) * 4 + dd * 16;
                float4 kv = *(const float4*)&kbase[(size_t)(m0 + r) * D + d4];
                Ks[(d4+0)*68 + r] = kv.x; Ks[(d4+1)*68 + r] = kv.y;
                Ks[(d4+2)*68 + r] = kv.z; Ks[(d4+3)*68 + r] = kv.w;
                float4 vv = *(const float4*)&vbase[(size_t)(m0 + r) * D + d4];
                *(float4*)&Vs[r * 68 + d4] = vv;
            }
        }
        __syncthreads();

        // S = (Q*SCALE).K^T (4x4 per thread)
        float s[4][4] = {};
        #pragma unroll 8
        for (int d = 0; d < 64; d++) {
            float4 a  = *(const float4*)&Qs[d * 68 + ty * 4];
            float4 bq = *(const float4*)&Ks[d * 68 + tx * 4];
            s[0][0] += a.x*bq.x; s[0][1] += a.x*bq.y; s[0][2] += a.x*bq.z; s[0][3] += a.x*bq.w;
            s[1][0] += a.y*bq.x; s[1][1] += a.y*bq.y; s[1][2] += a.y*bq.z; s[1][3] += a.y*bq.w;
            s[2][0] += a.z*bq.x; s[2][1] += a.z*bq.y; s[2][2] += a.z*bq.z; s[2][3] += a.z*bq.w;
            s[3][0] += a.w*bq.x; s[3][1] += a.w*bq.y; s[3][2] += a.w*bq.z; s[3][3] += a.w*bq.w;
        }

        // key-mask in registers
        #pragma unroll
        for (int j = 0; j < 4; j++) {
            bool km = ymb[m0 + tx * 4 + j] != 0;
            if (km) { s[0][j] = NEGV; s[1][j] = NEGV; s[2][j] = NEGV; s[3][j] = NEGV; }
        }

        // online softmax in registers (reduce across the 16 tx lanes)
        #pragma unroll
        for (int i = 0; i < 4; i++) {
            float mx = fmaxf(fmaxf(s[i][0], s[i][1]), fmaxf(s[i][2], s[i][3]));
            mx = fmaxf(mx, __shfl_xor_sync(0xffffffffu, mx, 1));
            mx = fmaxf(mx, __shfl_xor_sync(0xffffffffu, mx, 2));
            mx = fmaxf(mx, __shfl_xor_sync(0xffffffffu, mx, 4));
            mx = fmaxf(mx, __shfl_xor_sync(0xffffffffu, mx, 8));
            float mnew = fmaxf(mi[i], mx);
            float corr = __expf(mi[i] - mnew);
            float p0 = __expf(s[i][0] - mnew);
            float p1 = __expf(s[i][1] - mnew);
            float p2 = __expf(s[i][2] - mnew);
            float p3 = __expf(s[i][3] - mnew);
            int r = ty * 4 + i;
            Ss[(tx*4+0)*68 + r] = p0;
            Ss[(tx*4+1)*68 + r] = p1;
            Ss[(tx*4+2)*68 + r] = p2;
            Ss[(tx*4+3)*68 + r] = p3;
            float sum = (p0 + p1) + (p2 + p3);
            sum += __shfl_xor_sync(0xffffffffu, sum, 1);
            sum += __shfl_xor_sync(0xffffffffu, sum, 2);
            sum += __shfl_xor_sync(0xffffffffu, sum, 4);
            sum += __shfl_xor_sync(0xffffffffu, sum, 8);
            li[i] = li[i] * corr + sum;
            mi[i] = mnew;
            acc[i][0] *= corr; acc[i][1] *= corr; acc[i][2] *= corr; acc[i][3] *= corr;
        }
        __syncthreads();   // Ss visible to all before PV

        // acc += P.V
        #pragma unroll 8
        for (int m = 0; m < 64; m++) {
            float4 a  = *(const float4*)&Ss[m * 68 + ty * 4];
            float4 bv = *(const float4*)&Vs[m * 68 + tx * 4];
            acc[0][0] += a.x*bv.x; acc[0][1] += a.x*bv.y; acc[0][2] += a.x*bv.z; acc[0][3] += a.x*bv.w;
            acc[1][0] += a.y*bv.x; acc[1][1] += a.y*bv.y; acc[1][2] += a.y*bv.z; acc[1][3] += a.y*bv.w;
            acc[2][0] += a.z*bv.x; acc[2][1] += a.z*bv.y; acc[2][2] += a.z*bv.z; acc[2][3] += a.z*bv.w;
            acc[3][0] += a.w*bv.x; acc[3][1] += a.w*bv.y; acc[3][2] += a.w*bv.z; acc[3][3] += a.w*bv.w;
        }
    }

    // Writeout: att = acc / li, query-masked rows -> 0
    float* obase = att + ((size_t)b * NN + n0) * D + h * DS;
    #pragma unroll
    for (int i = 0; i < 4; i++) {
        int r = ty * 4 + i;
        float inv = 1.f / li[i];
        bool qm = xmb[n0 + r] != 0;
        float4 o;
        o.x = qm ? 0.f : acc[i][0] * inv;
        o.y = qm ? 0.f : acc[i][1] * inv;
        o.z = qm ? 0.f : acc[i][2] * inv;
        o.w = qm ? 0.f : acc[i][3] * inv;
        *(float4*)&obase[(size_t)r * D + tx * 4] = o;
    }
}

// ---------------------------------------------------------------------------
// out = LN(a' + b) * g + be
// mode bit0: zero OUTPUT rows where mask; bit1: zero `a` INPUT rows where mask
// ---------------------------------------------------------------------------
__global__ void __launch_bounds__(128) add_ln_k(
    const float* __restrict__ a, const float* __restrict__ bsrc,
    const float* __restrict__ g, const float* __restrict__ be,
    const int* __restrict__ xmask, int mode,
    float* __restrict__ out)
{
    int row = blockIdx.x;
    int t = threadIdx.x;
    const float* ar = a + (size_t)row * D;
    const float* br = bsrc + (size_t)row * D;
    bool rowmask = xmask[row] != 0;
    bool maska = (mode & 2) && rowmask;

    float vals[4];
    float s = 0.f;
    #pragma unroll
    for (int i = 0; i < 4; i++) {
        float av = maska ? 0.f : ar[t + i * 128];
        vals[i] = av + br[t + i * 128];
        s += vals[i];
    }
    __shared__ float red[4];
    #pragma unroll
    for (int o = 16; o; o >>= 1) s += __shfl_xor_sync(0xffffffffu, s, o);
    if ((t & 31) == 0) red[t >> 5] = s;
    __syncthreads();
    float mu = (red[0] + red[1] + red[2] + red[3]) * (1.f / 512.f);

    float s2 = 0.f;
    #pragma unroll
    for (int i = 0; i < 4; i++) { float d = vals[i] - mu; s2 += d * d; }
    __syncthreads();
    #pragma unroll
    for (int o = 16; o; o >>= 1) s2 += __shfl_xor_sync(0xffffffffu, s2, o);
    if ((t & 31) == 0) red[t >> 5] = s2;
    __syncthreads();
    float inv = rsqrtf((red[0] + red[1] + red[2] + red[3]) * (1.f / 512.f) + 1e-5f);

    bool maskout = (mode & 1) && rowmask;
    #pragma unroll
    for (int i = 0; i < 4; i++) {
        int c = t + i * 128;
        out[(size_t)row * D + c] = maskout ? 0.f : (vals[i] - mu) * inv * g[c] + be[c];
    }
}

// ---------------------------------------------------------------------------
extern "C" void kernel_launch(void* const* d_in, const int* in_sizes, int n_in,
                              void* d_out, int out_size)
{
    const float* x  = (const float*)d_in[0];
    const float* y  = (const float*)d_in[1];
    const int* xm = (const int*)d_in[2];
    const int* ym = (const int*)d_in[3];
    const float* Wq = (const float*)d_in[4];
    const float* Wk = (const float*)d_in[5];
    const float* Wv = (const float*)d_in[6];
    const float* Wo = (const float*)d_in[7];
    const float* W1 = (const float*)d_in[8];
    const float* b1 = (const float*)d_in[9];
    const float* W2 = (const float*)d_in[10];
    const float* b2 = (const float*)d_in[11];
    const float* g1 = (const float*)d_in[12];
    const float* be1= (const float*)d_in[13];
    const float* g2 = (const float*)d_in[14];
    const float* be2= (const float*)d_in[15];
    float* out = (float*)d_out;

    float *q, *k, *v, *att, *t1, *t2;
    cudaGetSymbolAddress((void**)&q,   S_q);
    cudaGetSymbolAddress((void**)&k,   S_k);
    cudaGetSymbolAddress((void**)&v,   S_v);
    cudaGetSymbolAddress((void**)&att, S_att);
    cudaGetSymbolAddress((void**)&t1,  S_t1);
    cudaGetSymbolAddress((void**)&t2,  S_t2);

    cudaFuncSetAttribute(attn_k, cudaFuncAttributeMaxDynamicSharedMemorySize, 70000);
    const int smem_attn = (4 * 64 * 68) * sizeof(float); // 69632 B

    dim3 gg(4, 64);   // 128x128 tiles: 4 col-tiles x 64 row-tiles
    sgemm128<4><<<gg, 256>>>(x, Wq, nullptr, xm, q);
    sgemm128<4><<<gg, 256>>>(y, Wk, nullptr, ym, k);
    sgemm128<4><<<gg, 256>>>(y, Wv, nullptr, ym, v);

    dim3 ga(16, 64);  // 16 q-tiles x (B*H)
    attn_k<<<ga, 256, smem_attn>>>(q, k, v, xm, ym, att);

    sgemm128<0><<<gg, 256>>>(att, Wo, nullptr, nullptr, t1);   // t1 = att@Wo
    add_ln_k<<<ROWS, 128>>>(x, t1, g1, be1, xm, 2, t2);        // t2 = LN1(x_masked + t1)
    sgemm128<3><<<gg, 256>>>(t2, W1, b1, nullptr, q);          // q = relu(t2@W1+b1)
    sgemm128<1><<<gg, 256>>>(q, W2, b2, nullptr, k);           // k = ff
    add_ln_k<<<ROWS, 128>>>(t2, k, g2, be2, xm, 1, out);       // out = LN2(t2+ff), masked
}

// round 5
// speedup vs baseline: 1.1780x; 1.0600x over previous
#include <cuda_runtime.h>
#include <math.h>

#define BB 8
#define NN 1024
#define MM 1024
#define D  512
#define HH 8
#define DS 64
#define ROWS (BB*NN)          // 8192
#define NEGV (-1e38f)
#define SCALE 0.04419417382415922f   // 1/sqrt(512)

typedef unsigned long long ull;

// packed f32x2 helpers (sm_100+)
__device__ __forceinline__ ull pk2(float lo, float hi) {
    ull r;
    asm("mov.b64 %0, {%1, %2};" : "=l"(r) : "f"(lo), "f"(hi));
    return r;
}
__device__ __forceinline__ float2 upk2(ull v) {
    float2 f;
    asm("mov.b64 {%0, %1}, %2;" : "=f"(f.x), "=f"(f.y) : "l"(v));
    return f;
}
#define FMA2(d, a, b) asm("fma.rn.f32x2 %0, %1, %2, %0;" : "+l"(d) : "l"(a), "l"(b))
#define MUL2(d, a)    asm("mul.rn.f32x2 %0, %0, %1;"    : "+l"(d) : "l"(a))

// Scratch (device globals; no allocation allowed)
__device__ float S_q  [ROWS*D];
__device__ float S_k  [ROWS*D];
__device__ float S_v  [ROWS*D];
__device__ float S_att[ROWS*D];
__device__ float S_t1 [ROWS*D];
__device__ float S_t2 [ROWS*D];

// ---------------------------------------------------------------------------
// SGEMM: C[ROWS,512] = A[ROWS,512] @ B[512,512]
// FLAGS: bit0 = +bias, bit1 = relu, bit2 = zero A rows where amask[row]!=0
// 128x128 tile, k-chunk 8, 256 threads, 8x8 microtile, FFMA2 inner,
// double-buffered smem.
// ---------------------------------------------------------------------------
template<int FLAGS>
__global__ void __launch_bounds__(256) sgemm128(
    const float* __restrict__ A, const float* __restrict__ Bmat,
    const float* __restrict__ bias, const int* __restrict__ amask,
    float* __restrict__ C)
{
    __shared__ float As[2][8][132];
    __shared__ float Bs[2][8][132];
    const int t  = threadIdx.x;
    const int tx = t & 15, ty = t >> 4;
    const int row0 = blockIdx.y * 128, col0 = blockIdx.x * 128;
    const int ar = t >> 1, ak = (t & 1) * 4;    // A: 2 threads/row, 8 k-cols
    const int bk = t >> 5, bn = (t & 31) * 4;   // B: 8 k-rows, 32 threads/row

    const bool am = (FLAGS & 4) && (amask[row0 + ar] != 0);
    const float* Aptr = A + (size_t)(row0 + ar) * D + ak;
    const float* Bptr = Bmat + (size_t)bk * D + col0 + bn;

    float4 av = *(const float4*)Aptr;
    float4 bv = *(const float4*)Bptr;
    if (am) av = make_float4(0.f, 0.f, 0.f, 0.f);
    As[0][ak+0][ar] = av.x; As[0][ak+1][ar] = av.y;
    As[0][ak+2][ar] = av.z; As[0][ak+3][ar] = av.w;
    *(float4*)&Bs[0][bk][bn] = bv;
    __syncthreads();

    ull acc2[8][4] = {};   // 8 rows x 4 col-pairs

    #pragma unroll 1
    for (int c = 0; c < 64; c++) {
        int cur = c & 1;
        if (c < 63) {
            av = *(const float4*)(Aptr + (c + 1) * 8);
            bv = *(const float4*)(Bptr + (size_t)(c + 1) * 8 * D);
            if (am) av = make_float4(0.f, 0.f, 0.f, 0.f);
        }
        #pragma unroll
        for (int kk = 0; kk < 8; kk++) {
            float4 a0 = *(const float4*)&As[cur][kk][ty * 4];
            float4 a1 = *(const float4*)&As[cur][kk][64 + ty * 4];
            float4 b0 = *(const float4*)&Bs[cur][kk][tx * 4];
            float4 b1 = *(const float4*)&Bs[cur][kk][64 + tx * 4];
            ull bp0 = pk2(b0.x, b0.y), bp1 = pk2(b0.z, b0.w);
            ull bp2 = pk2(b1.x, b1.y), bp3 = pk2(b1.z, b1.w);
            float ra[8] = {a0.x,a0.y,a0.z,a0.w,a1.x,a1.y,a1.z,a1.w};
            #pragma unroll
            for (int i = 0; i < 8; i++) {
                ull ap = pk2(ra[i], ra[i]);
                FMA2(acc2[i][0], ap, bp0);
                FMA2(acc2[i][1], ap, bp1);
                FMA2(acc2[i][2], ap, bp2);
                FMA2(acc2[i][3], ap, bp3);
            }
        }
        if (c < 63) {
            int nxt = cur ^ 1;
            As[nxt][ak+0][ar] = av.x; As[nxt][ak+1][ar] = av.y;
            As[nxt][ak+2][ar] = av.z; As[nxt][ak+3][ar] = av.w;
            *(float4*)&Bs[nxt][bk][bn] = bv;
            __syncthreads();
        }
    }

    #pragma unroll
    for (int i = 0; i < 8; i++) {
        int row = row0 + ((i < 4) ? (ty * 4 + i) : (64 + ty * 4 + i - 4));
        #pragma unroll
        for (int cb = 0; cb < 2; cb++) {
            int col = col0 + cb * 64 + tx * 4;
            float2 v0 = upk2(acc2[i][cb * 2 + 0]);
            float2 v1 = upk2(acc2[i][cb * 2 + 1]);
            float vv[4] = {v0.x, v0.y, v1.x, v1.y};
            #pragma unroll
            for (int j = 0; j < 4; j++) {
                if (FLAGS & 1) vv[j] += bias[col + j];
                if (FLAGS & 2) vv[j] = fmaxf(vv[j], 0.f);
            }
            *(float4*)&C[(size_t)row * D + col] =
                make_float4(vv[0], vv[1], vv[2], vv[3]);
        }
    }
}

// ---------------------------------------------------------------------------
// Flash attention: one CTA = (b,h, 128-query tile). Keys in chunks of 64.
// Thread grid 16x16: each thread 8 queries (ty) x 4 keys / 4 dims (tx).
// Online softmax in registers (shfl over the 16 tx lanes). FFMA2 inner loops.
// ---------------------------------------------------------------------------
#define QT 128
__global__ void __launch_bounds__(256) attn_k(
    const float* __restrict__ q, const float* __restrict__ k,
    const float* __restrict__ v,
    const int* __restrict__ xmask,
    const int* __restrict__ ymask,
    float* __restrict__ att)
{
    extern __shared__ float sm[];
    float* Qs = sm;               // [d=64][q=132]  pre-scaled
    float* Ks = Qs + 64 * 132;    // [d=64][k=68]
    float* Vs = Ks + 64 * 68;     // [m=64][d=68]
    float* Ss = Vs + 64 * 68;     // [k=64][q=132]  (exp'd P)

    const int bh = blockIdx.y;
    const int b  = bh >> 3, h = bh & 7;
    const int n0 = blockIdx.x * QT;
    const int t  = threadIdx.x;
    const int tx = t & 15, ty = t >> 4;

    const float* qbase = q + ((size_t)b * NN + n0) * D + h * DS;
    const float* kbase = k + (size_t)b * MM * D + h * DS;
    const float* vbase = v + (size_t)b * MM * D + h * DS;
    const int* ymb = ymask + b * MM;
    const int* xmb = xmask + b * NN;

    // Load Q tile (128 x 64) transposed into [d][q], scaled
    {
        int r = t >> 1;
        #pragma unroll
        for (int dd = 0; dd < 8; dd++) {
            int d4 = (t & 1) * 4 + dd * 8;
            float4 qa = *(const float4*)&qbase[(size_t)r * D + d4];
            Qs[(d4+0)*132 + r] = qa.x * SCALE; Qs[(d4+1)*132 + r] = qa.y * SCALE;
            Qs[(d4+2)*132 + r] = qa.z * SCALE; Qs[(d4+3)*132 + r] = qa.w * SCALE;
        }
    }

    float mi[8], li[8];
    #pragma unroll
    for (int i = 0; i < 8; i++) { mi[i] = -3.0e38f; li[i] = 0.f; }
    ull acc2[8][2] = {};   // 8 q-rows x 2 d-pairs (4 dims)

    for (int m0 = 0; m0 < MM; m0 += 64) {
        __syncthreads();   // protect Ks/Vs/Ss from previous iteration readers
        {
            int r = t >> 2;
            #pragma unroll
            for (int dd = 0; dd < 4; dd++) {
                int d4 = (t & 3) * 4 + dd * 16;
                float4 kv = *(const float4*)&kbase[(size_t)(m0 + r) * D + d4];
                Ks[(d4+0)*68 + r] = kv.x; Ks[(d4+1)*68 + r] = kv.y;
                Ks[(d4+2)*68 + r] = kv.z; Ks[(d4+3)*68 + r] = kv.w;
                float4 vv = *(const float4*)&vbase[(size_t)(m0 + r) * D + d4];
                *(float4*)&Vs[r * 68 + d4] = vv;
            }
        }
        __syncthreads();

        // S = (Q*SCALE).K^T : 8 q-rows x 4 keys per thread
        ull s2[8][2] = {};
        #pragma unroll 4
        for (int d = 0; d < 64; d++) {
            float4 q0 = *(const float4*)&Qs[d * 132 + ty * 8];
            float4 q1 = *(const float4*)&Qs[d * 132 + ty * 8 + 4];
            float4 kq = *(const float4*)&Ks[d * 68 + tx * 4];
            ull kp0 = pk2(kq.x, kq.y), kp1 = pk2(kq.z, kq.w);
            float qa[8] = {q0.x,q0.y,q0.z,q0.w,q1.x,q1.y,q1.z,q1.w};
            #pragma unroll
            for (int i = 0; i < 8; i++) {
                ull ap = pk2(qa[i], qa[i]);
                FMA2(s2[i][0], ap, kp0);
                FMA2(s2[i][1], ap, kp1);
            }
        }

        // unpack + key-mask
        float s[8][4];
        int km0 = ymb[m0 + tx * 4 + 0], km1 = ymb[m0 + tx * 4 + 1];
        int km2 = ymb[m0 + tx * 4 + 2], km3 = ymb[m0 + tx * 4 + 3];
        #pragma unroll
        for (int i = 0; i < 8; i++) {
            float2 v0 = upk2(s2[i][0]);
            float2 v1 = upk2(s2[i][1]);
            s[i][0] = km0 ? NEGV : v0.x;
            s[i][1] = km1 ? NEGV : v0.y;
            s[i][2] = km2 ? NEGV : v1.x;
            s[i][3] = km3 ? NEGV : v1.y;
        }

        // online softmax in registers (reduce across 16 tx lanes)
        #pragma unroll
        for (int i = 0; i < 8; i++) {
            float mx = fmaxf(fmaxf(s[i][0], s[i][1]), fmaxf(s[i][2], s[i][3]));
            mx = fmaxf(mx, __shfl_xor_sync(0xffffffffu, mx, 1));
            mx = fmaxf(mx, __shfl_xor_sync(0xffffffffu, mx, 2));
            mx = fmaxf(mx, __shfl_xor_sync(0xffffffffu, mx, 4));
            mx = fmaxf(mx, __shfl_xor_sync(0xffffffffu, mx, 8));
            float mnew = fmaxf(mi[i], mx);
            float corr = __expf(mi[i] - mnew);
            float p0 = __expf(s[i][0] - mnew);
            float p1 = __expf(s[i][1] - mnew);
            float p2 = __expf(s[i][2] - mnew);
            float p3 = __expf(s[i][3] - mnew);
            int r = ty * 8 + i;
            Ss[(tx*4+0)*132 + r] = p0;
            Ss[(tx*4+1)*132 + r] = p1;
            Ss[(tx*4+2)*132 + r] = p2;
            Ss[(tx*4+3)*132 + r] = p3;
            float sum = (p0 + p1) + (p2 + p3);
            sum += __shfl_xor_sync(0xffffffffu, sum, 1);
            sum += __shfl_xor_sync(0xffffffffu, sum, 2);
            sum += __shfl_xor_sync(0xffffffffu, sum, 4);
            sum += __shfl_xor_sync(0xffffffffu, sum, 8);
            li[i] = li[i] * corr + sum;
            mi[i] = mnew;
            ull cp = pk2(corr, corr);
            MUL2(acc2[i][0], cp);
            MUL2(acc2[i][1], cp);
        }
        __syncthreads();   // Ss visible to all before PV

        // acc += P.V : 8 q-rows x 4 dims per thread
        #pragma unroll 4
        for (int m = 0; m < 64; m++) {
            float4 p0 = *(const float4*)&Ss[m * 132 + ty * 8];
            float4 p1 = *(const float4*)&Ss[m * 132 + ty * 8 + 4];
            float4 vv = *(const float4*)&Vs[m * 68 + tx * 4];
            ull vp0 = pk2(vv.x, vv.y), vp1 = pk2(vv.z, vv.w);
            float pa[8] = {p0.x,p0.y,p0.z,p0.w,p1.x,p1.y,p1.z,p1.w};
            #pragma unroll
            for (int i = 0; i < 8; i++) {
                ull ap = pk2(pa[i], pa[i]);
                FMA2(acc2[i][0], ap, vp0);
                FMA2(acc2[i][1], ap, vp1);
            }
        }
    }

    // Writeout: att = acc / li, query-masked rows -> 0
    float* obase = att + ((size_t)b * NN + n0) * D + h * DS;
    #pragma unroll
    for (int i = 0; i < 8; i++) {
        int r = ty * 8 + i;
        float inv = 1.f / li[i];
        bool qm = xmb[n0 + r] != 0;
        float2 a0 = upk2(acc2[i][0]);
        float2 a1 = upk2(acc2[i][1]);
        float4 o;
        o.x = qm ? 0.f : a0.x * inv;
        o.y = qm ? 0.f : a0.y * inv;
        o.z = qm ? 0.f : a1.x * inv;
        o.w = qm ? 0.f : a1.y * inv;
        *(float4*)&obase[(size_t)r * D + tx * 4] = o;
    }
}

// ---------------------------------------------------------------------------
// out = LN(a' + b) * g + be
// mode bit0: zero OUTPUT rows where mask; bit1: zero `a` INPUT rows where mask
// ---------------------------------------------------------------------------
__global__ void __launch_bounds__(128) add_ln_k(
    const float* __restrict__ a, const float* __restrict__ bsrc,
    const float* __restrict__ g, const float* __restrict__ be,
    const int* __restrict__ xmask, int mode,
    float* __restrict__ out)
{
    int row = blockIdx.x;
    int t = threadIdx.x;
    const float* ar = a + (size_t)row * D;
    const float* br = bsrc + (size_t)row * D;
    bool rowmask = xmask[row] != 0;
    bool maska = (mode & 2) && rowmask;

    float vals[4];
    float s = 0.f;
    #pragma unroll
    for (int i = 0; i < 4; i++) {
        float av = maska ? 0.f : ar[t + i * 128];
        vals[i] = av + br[t + i * 128];
        s += vals[i];
    }
    __shared__ float red[4];
    #pragma unroll
    for (int o = 16; o; o >>= 1) s += __shfl_xor_sync(0xffffffffu, s, o);
    if ((t & 31) == 0) red[t >> 5] = s;
    __syncthreads();
    float mu = (red[0] + red[1] + red[2] + red[3]) * (1.f / 512.f);

    float s2 = 0.f;
    #pragma unroll
    for (int i = 0; i < 4; i++) { float d = vals[i] - mu; s2 += d * d; }
    __syncthreads();
    #pragma unroll
    for (int o = 16; o; o >>= 1) s2 += __shfl_xor_sync(0xffffffffu, s2, o);
    if ((t & 31) == 0) red[t >> 5] = s2;
    __syncthreads();
    float inv = rsqrtf((red[0] + red[1] + red[2] + red[3]) * (1.f / 512.f) + 1e-5f);

    bool maskout = (mode & 1) && rowmask;
    #pragma unroll
    for (int i = 0; i < 4; i++) {
        int c = t + i * 128;
        out[(size_t)row * D + c] = maskout ? 0.f : (vals[i] - mu) * inv * g[c] + be[c];
    }
}

// ---------------------------------------------------------------------------
extern "C" void kernel_launch(void* const* d_in, const int* in_sizes, int n_in,
                              void* d_out, int out_size)
{
    const float* x  = (const float*)d_in[0];
    const float* y  = (const float*)d_in[1];
    const int* xm = (const int*)d_in[2];
    const int* ym = (const int*)d_in[3];
    const float* Wq = (const float*)d_in[4];
    const float* Wk = (const float*)d_in[5];
    const float* Wv = (const float*)d_in[6];
    const float* Wo = (const float*)d_in[7];
    const float* W1 = (const float*)d_in[8];
    const float* b1 = (const float*)d_in[9];
    const float* W2 = (const float*)d_in[10];
    const float* b2 = (const float*)d_in[11];
    const float* g1 = (const float*)d_in[12];
    const float* be1= (const float*)d_in[13];
    const float* g2 = (const float*)d_in[14];
    const float* be2= (const float*)d_in[15];
    float* out = (float*)d_out;

    float *q, *k, *v, *att, *t1, *t2;
    cudaGetSymbolAddress((void**)&q,   S_q);
    cudaGetSymbolAddress((void**)&k,   S_k);
    cudaGetSymbolAddress((void**)&v,   S_v);
    cudaGetSymbolAddress((void**)&att, S_att);
    cudaGetSymbolAddress((void**)&t1,  S_t1);
    cudaGetSymbolAddress((void**)&t2,  S_t2);

    const int smem_attn = (64*132 + 64*68 + 64*68 + 64*132) * sizeof(float); // 102400
    cudaFuncSetAttribute(attn_k, cudaFuncAttributeMaxDynamicSharedMemorySize, smem_attn);

    dim3 gg(4, 64);   // 128x128 tiles
    sgemm128<4><<<gg, 256>>>(x, Wq, nullptr, xm, q);
    sgemm128<4><<<gg, 256>>>(y, Wk, nullptr, ym, k);
    sgemm128<4><<<gg, 256>>>(y, Wv, nullptr, ym, v);

    dim3 ga(8, 64);   // 8 q-tiles (128 each) x (B*H)
    attn_k<<<ga, 256, smem_attn>>>(q, k, v, xm, ym, att);

    sgemm128<0><<<gg, 256>>>(att, Wo, nullptr, nullptr, t1);   // t1 = att@Wo
    add_ln_k<<<ROWS, 128>>>(x, t1, g1, be1, xm, 2, t2);        // t2 = LN1(x_masked + t1)
    sgemm128<3><<<gg, 256>>>(t2, W1, b1, nullptr, q);          // q = relu(t2@W1+b1)
    sgemm128<1><<<gg, 256>>>(q, W2, b2, nullptr, k);           // k = ff
    add_ln_k<<<ROWS, 128>>>(t2, k, g2, be2, xm, 1, out);       // out = LN2(t2+ff), masked
}